// round 3
// baseline (speedup 1.0000x reference)
#include <cuda_runtime.h>
#include <math.h>

// Problem constants
#define BB 512
#define NN 128
#define DD 512
#define HH 8
#define DH 64
#define TWO_D 1024
#define STEPS 6

// ---------------- scratch (device globals; no allocation allowed) ----------
__device__ __align__(16) float g_hs[(size_t)BB * NN * DD];   // [B,N,D]
__device__ __align__(16) float g_m[BB * TWO_D];              // [B,2D]
__device__ __align__(16) float g_c[BB * DD];                 // [B,D]
__device__ __align__(16) float g_gpre[BB * 4 * DD];          // [B,2048] (i|f|c|o)
__device__ __align__(16) float g_query[BB * DD];             // [B,D]
__device__ __align__(16) float g_wpack[TWO_D * 4 * DD];      // [1024,2048]

__device__ __forceinline__ float sigmoidf_(float x) { return 1.0f / (1.0f + expf(-x)); }

// ---------------- generic fp32 SGEMM, 2-stage prefetch, float4 loads --------
// Requires: BK % 4 == 0, lda/ldb multiples of 4, A/B 16B-aligned,
// M%BM==0, N%BN==0, K%BK==0, and (BM*BK) and (BK*BN) divisible by 4*NT.
template<int BM, int BN, int BK, int TM, int TN>
__global__ void __launch_bounds__((BM / TM) * (BN / TN))
sgemm_kernel(int K,
             const float* __restrict__ A, int lda,
             const float* __restrict__ B, int ldb,
             float* __restrict__ C, int ldc,
             const float* __restrict__ bias)
{
    constexpr int NT    = (BM / TM) * (BN / TN);
    constexpr int AVEC  = (BM * BK) / (4 * NT);   // float4 A loads per thread
    constexpr int BVEC  = (BK * BN) / (4 * NT);   // float4 B loads per thread
    static_assert(AVEC >= 1 && BVEC >= 1, "tile too small");
    static_assert((BM * BK) % (4 * NT) == 0 && (BK * BN) % (4 * NT) == 0, "vec");

    __shared__ float As[BK][BM];
    __shared__ float Bs[BK][BN];

    const int t  = threadIdx.x;
    const int bm = blockIdx.y * BM;
    const int bn = blockIdx.x * BN;
    const int tx = t % (BN / TN);
    const int ty = t / (BN / TN);
    const int rm = ty * TM;
    const int rn = tx * TN;

    float acc[TM][TN];
#pragma unroll
    for (int i = 0; i < TM; i++)
#pragma unroll
        for (int j = 0; j < TN; j++) acc[i][j] = 0.0f;

    float4 ra[AVEC], rb[BVEC];

    // ---- load first tile (k0 = 0) ----
#pragma unroll
    for (int i = 0; i < AVEC; i++) {
        int idx = (t + i * NT) * 4;          // flat float index in BM*BK
        int r = idx / BK, c = idx % BK;      // c multiple of 4
        float4 v = *(const float4*)&A[(size_t)(bm + r) * lda + c];
        As[c + 0][r] = v.x; As[c + 1][r] = v.y; As[c + 2][r] = v.z; As[c + 3][r] = v.w;
    }
#pragma unroll
    for (int i = 0; i < BVEC; i++) {
        int idx = (t + i * NT) * 4;          // flat float index in BK*BN
        int r = idx / BN, c = idx % BN;
        *(float4*)&Bs[r][c] = *(const float4*)&B[(size_t)r * ldb + bn + c];
    }
    __syncthreads();

    for (int k0 = 0; k0 < K; k0 += BK) {
        const int kn = k0 + BK;
        if (kn < K) {
#pragma unroll
            for (int i = 0; i < AVEC; i++) {
                int idx = (t + i * NT) * 4;
                int r = idx / BK, c = idx % BK;
                ra[i] = *(const float4*)&A[(size_t)(bm + r) * lda + kn + c];
            }
#pragma unroll
            for (int i = 0; i < BVEC; i++) {
                int idx = (t + i * NT) * 4;
                int r = idx / BN, c = idx % BN;
                rb[i] = *(const float4*)&B[(size_t)(kn + r) * ldb + bn + c];
            }
        }
#pragma unroll
        for (int k = 0; k < BK; k++) {
            float fa[TM], fb[TN];
#pragma unroll
            for (int i = 0; i < TM; i++) fa[i] = As[k][rm + i];
#pragma unroll
            for (int j = 0; j < TN; j++) fb[j] = Bs[k][rn + j];
#pragma unroll
            for (int i = 0; i < TM; i++)
#pragma unroll
                for (int j = 0; j < TN; j++)
                    acc[i][j] = fmaf(fa[i], fb[j], acc[i][j]);
        }
        __syncthreads();
        if (kn < K) {
#pragma unroll
            for (int i = 0; i < AVEC; i++) {
                int idx = (t + i * NT) * 4;
                int r = idx / BK, c = idx % BK;
                As[c + 0][r] = ra[i].x; As[c + 1][r] = ra[i].y;
                As[c + 2][r] = ra[i].z; As[c + 3][r] = ra[i].w;
            }
#pragma unroll
            for (int i = 0; i < BVEC; i++) {
                int idx = (t + i * NT) * 4;
                int r = idx / BN, c = idx % BN;
                *(float4*)&Bs[r][c] = rb[i];
            }
            __syncthreads();
        }
    }

#pragma unroll
    for (int j = 0; j < TN; j++) {
        const float bv = bias ? bias[bn + rn + j] : 0.0f;
#pragma unroll
        for (int i = 0; i < TM; i++) {
            C[(size_t)(bm + rm + i) * ldc + bn + rn + j] = acc[i][j] + bv;
        }
    }
}

// ---------------- small helper kernels -------------------------------------
__global__ void zero_mc_kernel() {
    int i = blockIdx.x * blockDim.x + threadIdx.x;
    if (i < BB * TWO_D) g_m[i] = 0.0f;
    if (i < BB * DD)    g_c[i] = 0.0f;
}

__global__ void pack_w_kernel(const float* __restrict__ wi, const float* __restrict__ wf,
                              const float* __restrict__ wc, const float* __restrict__ wo) {
    int i = blockIdx.x * blockDim.x + threadIdx.x;   // over 1024*2048
    if (i >= TWO_D * 4 * DD) return;
    int k   = i >> 11;        // / 2048
    int col = i & 2047;
    int g   = col >> 9;       // / 512
    int j   = col & 511;
    const float* w = (g == 0) ? wi : (g == 1) ? wf : (g == 2) ? wc : wo;
    g_wpack[i] = w[k * DD + j];
}

// gate combine: c_new, m_lstm from packed preactivations
__global__ void combine_kernel(const float* __restrict__ bi, const float* __restrict__ bf,
                               const float* __restrict__ bc, const float* __restrict__ bo) {
    const int b = blockIdx.x;       // [0,512)
    const int j = threadIdx.x;      // [0,512)
    const size_t base = (size_t)b * (4 * DD);
    float ip = g_gpre[base + j]            + bi[j];
    float fp = g_gpre[base + DD + j]       + bf[j];
    float cp = g_gpre[base + 2 * DD + j]   + bc[j];
    float op = g_gpre[base + 3 * DD + j]   + bo[j];
    float cold = g_c[b * DD + j];
    float cn = sigmoidf_(fp) * cold + sigmoidf_(ip) * tanhf(cp);
    g_c[b * DD + j] = cn;
    g_m[b * TWO_D + j] = sigmoidf_(op) * tanhf(cn);   // m_lstm into first half of m
}

// fused attention: energies -> softmax -> read, one pass over hs tile in smem
__global__ void __launch_bounds__(128)
attention_kernel(const float* __restrict__ mask, const float* __restrict__ att_v) {
    __shared__ float hs_s[NN][DH + 1];   // padded to kill bank conflicts
    __shared__ float qv[DH];
    __shared__ float av[DH];
    __shared__ float red[NN];
    __shared__ float attn[NN];

    const int t = threadIdx.x;           // 128 threads
    const int b = blockIdx.x >> 3;
    const int h = blockIdx.x & 7;

    const float* hs_base = g_hs + (size_t)b * NN * DD + h * DH;
    for (int i = t; i < NN * DH; i += 128) {
        int n = i >> 6, d = i & 63;
        hs_s[n][d] = hs_base[(size_t)n * DD + d];
    }
    if (t < DH) {
        qv[t] = g_query[b * DD + h * DH + t];
        av[t] = att_v[h * DH + t];
    }
    __syncthreads();

    // energies for row n = t
    float e = 0.0f;
#pragma unroll 8
    for (int d = 0; d < DH; d++) {
        e += tanhf(qv[d] + hs_s[t][d]) * av[d];
    }
    e += (1.0f - mask[b * NN + t]) * (-1e10f);

    // max reduce
    red[t] = e;
    __syncthreads();
#pragma unroll
    for (int s = 64; s > 0; s >>= 1) {
        if (t < s) red[t] = fmaxf(red[t], red[t + s]);
        __syncthreads();
    }
    const float mx = red[0];
    __syncthreads();

    // exp + sum reduce
    float p = expf(e - mx);
    attn[t] = p;
    red[t]  = p;
    __syncthreads();
#pragma unroll
    for (int s = 64; s > 0; s >>= 1) {
        if (t < s) red[t] += red[t + s];
        __syncthreads();
    }
    const float inv_sum = 1.0f / red[0];
    __syncthreads();
    attn[t] *= inv_sum;
    __syncthreads();

    // read: threads 0..63 each produce one dh
    if (t < DH) {
        float r = 0.0f;
#pragma unroll 8
        for (int n = 0; n < NN; n++) {
            r += attn[n] * hs_s[n][t];
        }
        g_m[b * TWO_D + DD + h * DH + t] = r;   // read into second half of m
    }
}

__global__ void copy_out_kernel(float* __restrict__ out) {
    int i = blockIdx.x * blockDim.x + threadIdx.x;
    if (i < BB * TWO_D) out[i] = g_m[i];
}

// ---------------- launcher ---------------------------------------------------
extern "C" void kernel_launch(void* const* d_in, const int* in_sizes, int n_in,
                              void* d_out, int out_size) {
    const float* X     = (const float*)d_in[0];   // hidden_states [B,N,D]
    const float* mask  = (const float*)d_in[1];   // [B,N]
    const float* fc_w  = (const float*)d_in[2];   // [D,D]
    const float* fc_b  = (const float*)d_in[3];   // [D]
    const float* w_im  = (const float*)d_in[4];
    const float* b_i   = (const float*)d_in[5];
    const float* w_fm  = (const float*)d_in[6];
    const float* b_f   = (const float*)d_in[7];
    const float* w_cm  = (const float*)d_in[8];
    const float* b_c   = (const float*)d_in[9];
    const float* w_om  = (const float*)d_in[10];
    const float* b_o   = (const float*)d_in[11];
    const float* m2q   = (const float*)d_in[12];  // [D,D]
    const float* att_v = (const float*)d_in[13];  // [H,Dh]
    float* out = (float*)d_out;

    // scratch pointers for generic sgemm
    float *p_hs, *p_m, *p_gpre, *p_query, *p_wpack;
    cudaGetSymbolAddress((void**)&p_hs,    g_hs);
    cudaGetSymbolAddress((void**)&p_m,     g_m);
    cudaGetSymbolAddress((void**)&p_gpre,  g_gpre);
    cudaGetSymbolAddress((void**)&p_query, g_query);
    cudaGetSymbolAddress((void**)&p_wpack, g_wpack);

    // init recurrent state
    zero_mc_kernel<<<(BB * TWO_D + 255) / 256, 256>>>();

    // pack gate weights: [1024, 2048] = [w_im | w_fm | w_cm | w_om]
    pack_w_kernel<<<(TWO_D * 4 * DD + 255) / 256, 256>>>(w_im, w_fm, w_cm, w_om);

    // projection: hs = X @ fc_w + fc_b   (M=65536, N=512, K=512)
    {
        dim3 grid(DD / 128, (BB * NN) / 128);
        sgemm_kernel<128, 128, 8, 8, 8><<<grid, 256>>>(
            DD, X, DD, fc_w, DD, p_hs, DD, fc_b);
    }

    for (int step = 0; step < STEPS; step++) {
        // gates: [512,1024] @ [1024,2048] -> [512,2048]
        {
            dim3 grid((4 * DD) / 64, BB / 64);
            sgemm_kernel<64, 64, 16, 4, 4><<<grid, 256>>>(
                TWO_D, p_m, TWO_D, p_wpack, 4 * DD, p_gpre, 4 * DD, nullptr);
        }
        // gate nonlinearity + cell update -> m_lstm in m[:, :D]
        combine_kernel<<<BB, DD>>>(b_i, b_f, b_c, b_o);

        // query = m_lstm @ m_to_query  (A = m[:, :512] with lda=1024)
        {
            dim3 grid(DD / 64, BB / 64);
            sgemm_kernel<64, 64, 16, 4, 4><<<grid, 256>>>(
                DD, p_m, TWO_D, m2q, DD, p_query, DD, nullptr);
        }
        // fused attention -> read in m[:, D:2D]
        attention_kernel<<<BB * HH, 128>>>(mask, att_v);
    }

    copy_out_kernel<<<(BB * TWO_D + 255) / 256, 256>>>(out);
}

// round 6
// speedup vs baseline: 1.9591x; 1.9591x over previous
#include <cuda_runtime.h>
#include <cuda_bf16.h>
#include <math.h>
#include <stdint.h>

// Problem constants
#define BB 512
#define NN 128
#define DD 512
#define HH 8
#define DH 64
#define TWO_D 1024
#define STEPS 6

#define SWZ(off) ((off) ^ (((off) >> 3) & 0x70))

// ---------------- PTX helpers (sm_80+ features only; no tcgen05/TMA) --------
__device__ __forceinline__ void cp_async16(uint32_t smem_addr, const void* gptr) {
    asm volatile("cp.async.cg.shared.global [%0], [%1], 16;\n"
                 :: "r"(smem_addr), "l"(gptr));
}
__device__ __forceinline__ void cp_commit() {
    asm volatile("cp.async.commit_group;\n" ::: "memory");
}
template<int N> __device__ __forceinline__ void cp_wait() {
    asm volatile("cp.async.wait_group %0;\n" :: "n"(N) : "memory");
}
__device__ __forceinline__ void ldsm_x4(uint32_t* r, uint32_t addr) {
    asm volatile("ldmatrix.sync.aligned.m8n8.x4.shared.b16 {%0,%1,%2,%3}, [%4];\n"
                 : "=r"(r[0]), "=r"(r[1]), "=r"(r[2]), "=r"(r[3]) : "r"(addr));
}
__device__ __forceinline__ void mma_16816(float* c, const uint32_t* a, const uint32_t* b) {
    asm volatile("mma.sync.aligned.m16n8k16.row.col.f32.bf16.bf16.f32 "
                 "{%0,%1,%2,%3}, {%4,%5,%6,%7}, {%8,%9}, {%0,%1,%2,%3};\n"
                 : "+f"(c[0]), "+f"(c[1]), "+f"(c[2]), "+f"(c[3])
                 : "r"(a[0]), "r"(a[1]), "r"(a[2]), "r"(a[3]), "r"(b[0]), "r"(b[1]));
}

// ---------------- scratch (device globals) ----------------------------------
__device__ __align__(16) float g_hs[(size_t)BB * NN * DD];   // [B,N,D]
__device__ __align__(16) float g_m[BB * TWO_D];              // [B,2D] fp32
__device__ __align__(16) float g_c[BB * DD];                 // [B,D]
__device__ __align__(16) float g_gpre[BB * 4 * DD];          // [B,2048]
__device__ __align__(16) float g_query[BB * DD];             // [B,D]
// bf16 hi/lo operand copies
__device__ __align__(16) __nv_bfloat16 g_x_hi[(size_t)BB * NN * DD];
__device__ __align__(16) __nv_bfloat16 g_x_lo[(size_t)BB * NN * DD];
__device__ __align__(16) __nv_bfloat16 g_m_hi[BB * TWO_D];
__device__ __align__(16) __nv_bfloat16 g_m_lo[BB * TWO_D];
// packed transposed weights [N][K] bf16 hi/lo
__device__ __align__(16) __nv_bfloat16 g_fc_hi[DD * DD];
__device__ __align__(16) __nv_bfloat16 g_fc_lo[DD * DD];
__device__ __align__(16) __nv_bfloat16 g_wg_hi[4 * DD * TWO_D];
__device__ __align__(16) __nv_bfloat16 g_wg_lo[4 * DD * TWO_D];
__device__ __align__(16) __nv_bfloat16 g_q_hi[DD * DD];
__device__ __align__(16) __nv_bfloat16 g_q_lo[DD * DD];

__device__ __forceinline__ float sigmoidf_(float x) { return 1.0f / (1.0f + expf(-x)); }

// ---------------- tile copy: gmem bf16 [rows][ld] -> smem SW128 -------------
template<int ROWS>
__device__ __forceinline__ void copy_tile(uint32_t sbase, const __nv_bfloat16* __restrict__ g,
                                          int ldg, int r0, int k0, int t) {
#pragma unroll
    for (int v = t; v < ROWS * 8; v += 256) {
        int row = v >> 3, ch = v & 7;
        uint32_t off = SWZ((uint32_t)(row * 128 + ch * 16));
        cp_async16(sbase + off, g + (size_t)(r0 + row) * ldg + k0 + ch * 8);
    }
}

// ---------------- bf16-split HMMA GEMM --------------------------------------
// C[M,N] = (Ahi+Alo)[M,K] @ (Bhi+Blo)^T, B stored [N][K]. 3-term split, fp32 acc.
// Block BMxBN, K-block 64, double-buffered cp.async, 256 threads (8 warps).
template<int BM, int BN, int WM, int WN>
__global__ void __launch_bounds__(256, 1)
mma_gemm_kernel(int K,
                const __nv_bfloat16* __restrict__ Ahi, const __nv_bfloat16* __restrict__ Alo, int lda,
                const __nv_bfloat16* __restrict__ Bhi, const __nv_bfloat16* __restrict__ Blo, int ldb,
                float* __restrict__ C, int ldc, const float* __restrict__ bias)
{
    constexpr int WTM = BM / WM, WTN = BN / WN;
    constexpr int MT = WTM / 16, NT = WTN / 8, NP = NT / 2;
    constexpr int STAGE = (2 * BM + 2 * BN) * 128;
    static_assert(WM * WN == 8 && MT >= 1 && NP >= 1, "cfg");

    extern __shared__ char smem[];
    const int t = threadIdx.x, lane = t & 31, wid = t >> 5;
    const int wm = wid % WM, wn = wid / WM;
    const int m0 = blockIdx.y * BM, n0 = blockIdx.x * BN;
    const uint32_t sbase = (uint32_t)__cvta_generic_to_shared(smem);

    float c[MT][NT][4];
#pragma unroll
    for (int i = 0; i < MT; i++)
#pragma unroll
        for (int j = 0; j < NT; j++)
#pragma unroll
            for (int q = 0; q < 4; q++) c[i][j][q] = 0.0f;

    const int NB = K >> 6;

    auto issue = [&](int kb, int buf) {
        uint32_t st = sbase + (uint32_t)buf * STAGE;
        copy_tile<BM>(st,                           Ahi, lda, m0, kb * 64, t);
        copy_tile<BM>(st + BM * 128,                Alo, lda, m0, kb * 64, t);
        copy_tile<BN>(st + 2 * BM * 128,            Bhi, ldb, n0, kb * 64, t);
        copy_tile<BN>(st + 2 * BM * 128 + BN * 128, Blo, ldb, n0, kb * 64, t);
        cp_commit();
    };

    issue(0, 0);
    issue(1, 1);

    for (int kb = 0; kb < NB; kb++) {
        if (kb + 1 < NB) cp_wait<1>(); else cp_wait<0>();
        __syncthreads();
        const uint32_t st  = sbase + (uint32_t)(kb & 1) * STAGE;
        const uint32_t aHi = st, aLo = st + BM * 128;
        const uint32_t bHi = st + 2 * BM * 128, bLo = bHi + BN * 128;

#pragma unroll
        for (int s = 0; s < 4; s++) {
            uint32_t ahf[MT][4], alf[MT][4];
            const int      arow  = wm * WTM + (lane & 15);
            const uint32_t abyte = s * 32 + ((lane >> 4) << 4);
#pragma unroll
            for (int i = 0; i < MT; i++) {
                uint32_t off = SWZ((uint32_t)((arow + i * 16) * 128) + abyte);
                ldsm_x4(ahf[i], aHi + off);
                ldsm_x4(alf[i], aLo + off);
            }
            uint32_t bhf[NP][4], blf[NP][4];
            const int      brow  = wn * WTN + ((lane >> 4) << 3) + (lane & 7);
            const uint32_t bbyte = s * 32 + (((lane >> 3) & 1) << 4);
#pragma unroll
            for (int p = 0; p < NP; p++) {
                uint32_t off = SWZ((uint32_t)((brow + p * 16) * 128) + bbyte);
                ldsm_x4(bhf[p], bHi + off);
                ldsm_x4(blf[p], bLo + off);
            }
#pragma unroll
            for (int i = 0; i < MT; i++)
#pragma unroll
                for (int j = 0; j < NT; j++) {
                    const uint32_t* bh = &bhf[j >> 1][(j & 1) * 2];
                    const uint32_t* bl = &blf[j >> 1][(j & 1) * 2];
                    mma_16816(c[i][j], ahf[i], bh);
                    mma_16816(c[i][j], ahf[i], bl);
                    mma_16816(c[i][j], alf[i], bh);
                }
        }
        __syncthreads();
        if (kb + 2 < NB) issue(kb + 2, kb & 1);
    }

    // writeout
    const int wr = m0 + wm * WTM, wc = n0 + wn * WTN;
#pragma unroll
    for (int i = 0; i < MT; i++) {
        int r0 = wr + i * 16 + (lane >> 2);
#pragma unroll
        for (int j = 0; j < NT; j++) {
            int col = wc + j * 8 + (lane & 3) * 2;
            float bx = 0.0f, by = 0.0f;
            if (bias) { bx = bias[col]; by = bias[col + 1]; }
            float2 v0 = make_float2(c[i][j][0] + bx, c[i][j][1] + by);
            float2 v1 = make_float2(c[i][j][2] + bx, c[i][j][3] + by);
            *(float2*)&C[(size_t)r0 * ldc + col]       = v0;
            *(float2*)&C[(size_t)(r0 + 8) * ldc + col] = v1;
        }
    }
}

// ---------------- conversion / pack kernels ---------------------------------
__global__ void conv_x_kernel(const float* __restrict__ X) {
    int i = blockIdx.x * blockDim.x + threadIdx.x;      // over float4s
    const int n4 = (int)((size_t)BB * NN * DD / 4);
    if (i >= n4) return;
    float4 x = ((const float4*)X)[i];
    __nv_bfloat16 h0 = __float2bfloat16_rn(x.x), h1 = __float2bfloat16_rn(x.y);
    __nv_bfloat16 h2 = __float2bfloat16_rn(x.z), h3 = __float2bfloat16_rn(x.w);
    __nv_bfloat162 hh0(h0, h1), hh1(h2, h3);
    __nv_bfloat162 ll0(__float2bfloat16_rn(x.x - __bfloat162float(h0)),
                       __float2bfloat16_rn(x.y - __bfloat162float(h1)));
    __nv_bfloat162 ll1(__float2bfloat16_rn(x.z - __bfloat162float(h2)),
                       __float2bfloat16_rn(x.w - __bfloat162float(h3)));
    ((uint2*)g_x_hi)[i] = make_uint2(*(uint32_t*)&hh0, *(uint32_t*)&hh1);
    ((uint2*)g_x_lo)[i] = make_uint2(*(uint32_t*)&ll0, *(uint32_t*)&ll1);
}

__global__ void pack_fc_kernel(const float* __restrict__ w) {    // [K][N] -> [N][K]
    int i = blockIdx.x * blockDim.x + threadIdx.x;
    if (i >= DD * DD) return;
    int n = i >> 9, k = i & 511;
    float x = w[k * DD + n];
    __nv_bfloat16 h = __float2bfloat16_rn(x);
    g_fc_hi[i] = h;
    g_fc_lo[i] = __float2bfloat16_rn(x - __bfloat162float(h));
}
__global__ void pack_q_kernel(const float* __restrict__ w) {
    int i = blockIdx.x * blockDim.x + threadIdx.x;
    if (i >= DD * DD) return;
    int n = i >> 9, k = i & 511;
    float x = w[k * DD + n];
    __nv_bfloat16 h = __float2bfloat16_rn(x);
    g_q_hi[i] = h;
    g_q_lo[i] = __float2bfloat16_rn(x - __bfloat162float(h));
}
__global__ void pack_gates_kernel(const float* __restrict__ wi, const float* __restrict__ wf,
                                  const float* __restrict__ wc, const float* __restrict__ wo) {
    int i = blockIdx.x * blockDim.x + threadIdx.x;   // over 2048*1024 [n][k]
    if (i >= 4 * DD * TWO_D) return;
    int n = i >> 10, k = i & 1023;
    int g = n >> 9, j = n & 511;
    const float* w = (g == 0) ? wi : (g == 1) ? wf : (g == 2) ? wc : wo;
    float x = w[k * DD + j];
    __nv_bfloat16 h = __float2bfloat16_rn(x);
    g_wg_hi[i] = h;
    g_wg_lo[i] = __float2bfloat16_rn(x - __bfloat162float(h));
}

// ---------------- elementwise / attention ------------------------------------
__global__ void zero_mc_kernel() {
    int i = blockIdx.x * blockDim.x + threadIdx.x;
    if (i < BB * TWO_D) {
        g_m[i] = 0.0f;
        g_m_hi[i] = __float2bfloat16_rn(0.0f);
        g_m_lo[i] = __float2bfloat16_rn(0.0f);
    }
    if (i < BB * DD) g_c[i] = 0.0f;
}

__global__ void combine_kernel(const float* __restrict__ bi, const float* __restrict__ bf,
                               const float* __restrict__ bc, const float* __restrict__ bo) {
    const int b = blockIdx.x;
    const int j = threadIdx.x;
    const size_t base = (size_t)b * (4 * DD);
    float ip = g_gpre[base + j]           + bi[j];
    float fp = g_gpre[base + DD + j]      + bf[j];
    float cp = g_gpre[base + 2 * DD + j]  + bc[j];
    float op = g_gpre[base + 3 * DD + j]  + bo[j];
    float cold = g_c[b * DD + j];
    float cn = sigmoidf_(fp) * cold + sigmoidf_(ip) * tanhf(cp);
    g_c[b * DD + j] = cn;
    float v = sigmoidf_(op) * tanhf(cn);
    g_m[b * TWO_D + j] = v;
    __nv_bfloat16 h = __float2bfloat16_rn(v);
    g_m_hi[b * TWO_D + j] = h;
    g_m_lo[b * TWO_D + j] = __float2bfloat16_rn(v - __bfloat162float(h));
}

__global__ void __launch_bounds__(128)
attention_kernel(const float* __restrict__ mask, const float* __restrict__ att_v) {
    __shared__ float hs_s[NN][DH + 1];
    __shared__ float qv[DH];
    __shared__ float av[DH];
    __shared__ float red[NN];
    __shared__ float attn[NN];

    const int t = threadIdx.x;
    const int b = blockIdx.x >> 3;
    const int h = blockIdx.x & 7;

    const float* hs_base = g_hs + (size_t)b * NN * DD + h * DH;
    for (int i = t; i < NN * DH; i += 128) {
        int n = i >> 6, d = i & 63;
        hs_s[n][d] = hs_base[(size_t)n * DD + d];
    }
    if (t < DH) {
        qv[t] = g_query[b * DD + h * DH + t];
        av[t] = att_v[h * DH + t];
    }
    __syncthreads();

    float e = 0.0f;
#pragma unroll 8
    for (int d = 0; d < DH; d++) e += tanhf(qv[d] + hs_s[t][d]) * av[d];
    e += (1.0f - mask[b * NN + t]) * (-1e10f);

    red[t] = e;
    __syncthreads();
#pragma unroll
    for (int s = 64; s > 0; s >>= 1) {
        if (t < s) red[t] = fmaxf(red[t], red[t + s]);
        __syncthreads();
    }
    const float mx = red[0];
    __syncthreads();

    float p = expf(e - mx);
    attn[t] = p; red[t] = p;
    __syncthreads();
#pragma unroll
    for (int s = 64; s > 0; s >>= 1) {
        if (t < s) red[t] += red[t + s];
        __syncthreads();
    }
    const float inv_sum = 1.0f / red[0];
    __syncthreads();
    attn[t] *= inv_sum;
    __syncthreads();

    if (t < DH) {
        float r = 0.0f;
#pragma unroll 8
        for (int n = 0; n < NN; n++) r += attn[n] * hs_s[n][t];
        int col = DD + h * DH + t;
        g_m[b * TWO_D + col] = r;
        __nv_bfloat16 hh = __float2bfloat16_rn(r);
        g_m_hi[b * TWO_D + col] = hh;
        g_m_lo[b * TWO_D + col] = __float2bfloat16_rn(r - __bfloat162float(hh));
    }
}

__global__ void copy_out_kernel(float* __restrict__ out) {
    int i = blockIdx.x * blockDim.x + threadIdx.x;
    if (i < BB * TWO_D) out[i] = g_m[i];
}

// ---------------- launcher ----------------------------------------------------
extern "C" void kernel_launch(void* const* d_in, const int* in_sizes, int n_in,
                              void* d_out, int out_size) {
    const float* X     = (const float*)d_in[0];
    const float* mask  = (const float*)d_in[1];
    const float* fc_w  = (const float*)d_in[2];
    const float* fc_b  = (const float*)d_in[3];
    const float* w_im  = (const float*)d_in[4];
    const float* b_i   = (const float*)d_in[5];
    const float* w_fm  = (const float*)d_in[6];
    const float* b_f   = (const float*)d_in[7];
    const float* w_cm  = (const float*)d_in[8];
    const float* b_c   = (const float*)d_in[9];
    const float* w_om  = (const float*)d_in[10];
    const float* b_o   = (const float*)d_in[11];
    const float* m2q   = (const float*)d_in[12];
    const float* att_v = (const float*)d_in[13];
    float* out = (float*)d_out;

    float *p_hs, *p_gpre, *p_query;
    __nv_bfloat16 *p_x_hi, *p_x_lo, *p_m_hi, *p_m_lo;
    __nv_bfloat16 *p_fc_hi, *p_fc_lo, *p_wg_hi, *p_wg_lo, *p_q_hi, *p_q_lo;
    cudaGetSymbolAddress((void**)&p_hs,    g_hs);
    cudaGetSymbolAddress((void**)&p_gpre,  g_gpre);
    cudaGetSymbolAddress((void**)&p_query, g_query);
    cudaGetSymbolAddress((void**)&p_x_hi,  g_x_hi);
    cudaGetSymbolAddress((void**)&p_x_lo,  g_x_lo);
    cudaGetSymbolAddress((void**)&p_m_hi,  g_m_hi);
    cudaGetSymbolAddress((void**)&p_m_lo,  g_m_lo);
    cudaGetSymbolAddress((void**)&p_fc_hi, g_fc_hi);
    cudaGetSymbolAddress((void**)&p_fc_lo, g_fc_lo);
    cudaGetSymbolAddress((void**)&p_wg_hi, g_wg_hi);
    cudaGetSymbolAddress((void**)&p_wg_lo, g_wg_lo);
    cudaGetSymbolAddress((void**)&p_q_hi,  g_q_hi);
    cudaGetSymbolAddress((void**)&p_q_lo,  g_q_lo);

    // smem sizes per instantiation
    const int SM_PROJ  = (2 * 128 + 2 * 128) * 128 * 2;  // 131072
    const int SM_GATE  = (2 * 128 + 2 * 64)  * 128 * 2;  // 98304
    const int SM_QUERY = (2 * 64  + 2 * 64)  * 128 * 2;  // 65536
    cudaFuncSetAttribute((const void*)mma_gemm_kernel<128, 128, 2, 4>,
                         cudaFuncAttributeMaxDynamicSharedMemorySize, SM_PROJ);
    cudaFuncSetAttribute((const void*)mma_gemm_kernel<128, 64, 2, 4>,
                         cudaFuncAttributeMaxDynamicSharedMemorySize, SM_GATE);
    cudaFuncSetAttribute((const void*)mma_gemm_kernel<64, 64, 2, 4>,
                         cudaFuncAttributeMaxDynamicSharedMemorySize, SM_QUERY);

    zero_mc_kernel<<<(BB * TWO_D + 255) / 256, 256>>>();
    conv_x_kernel<<<((int)((size_t)BB * NN * DD / 4) + 255) / 256, 256>>>(X);
    pack_fc_kernel<<<(DD * DD + 255) / 256, 256>>>(fc_w);
    pack_q_kernel<<<(DD * DD + 255) / 256, 256>>>(m2q);
    pack_gates_kernel<<<(4 * DD * TWO_D + 255) / 256, 256>>>(w_im, w_fm, w_cm, w_om);

    // projection: hs = X @ fc_w + fc_b   (M=65536, N=512, K=512)
    {
        dim3 grid(DD / 128, (BB * NN) / 128);
        mma_gemm_kernel<128, 128, 2, 4><<<grid, 256, SM_PROJ>>>(
            DD, p_x_hi, p_x_lo, DD, p_fc_hi, p_fc_lo, DD, p_hs, DD, fc_b);
    }

    for (int step = 0; step < STEPS; step++) {
        // gates: m[512,1024] @ Wg^T -> gpre[512,2048]
        {
            dim3 grid((4 * DD) / 64, BB / 128);
            mma_gemm_kernel<128, 64, 2, 4><<<grid, 256, SM_GATE>>>(
                TWO_D, p_m_hi, p_m_lo, TWO_D, p_wg_hi, p_wg_lo, TWO_D,
                p_gpre, 4 * DD, nullptr);
        }
        combine_kernel<<<BB, DD>>>(b_i, b_f, b_c, b_o);

        // query = m_lstm @ m2q  (A = m_hi/lo[:, :512], lda=1024)
        {
            dim3 grid(DD / 64, BB / 64);
            mma_gemm_kernel<64, 64, 2, 4><<<grid, 256, SM_QUERY>>>(
                DD, p_m_hi, p_m_lo, TWO_D, p_q_hi, p_q_lo, DD,
                p_query, DD, nullptr);
        }
        attention_kernel<<<BB * HH, 128>>>(mask, att_v);
    }

    copy_out_kernel<<<(BB * TWO_D + 255) / 256, 256>>>(out);
}

// round 7
// speedup vs baseline: 1.9858x; 1.0136x over previous
#include <cuda_runtime.h>
#include <cuda_bf16.h>
#include <math.h>
#include <stdint.h>

// Problem constants
#define BB 512
#define NN 128
#define DD 512
#define HH 8
#define DH 64
#define TWO_D 1024
#define STEPS 6

#define SWZ(off) ((off) ^ (((off) >> 3) & 0x70))

// ---------------- PTX helpers (sm_80+ features only; no tcgen05/TMA) --------
__device__ __forceinline__ void cp_async16(uint32_t smem_addr, const void* gptr) {
    asm volatile("cp.async.cg.shared.global [%0], [%1], 16;\n"
                 :: "r"(smem_addr), "l"(gptr));
}
__device__ __forceinline__ void cp_commit() {
    asm volatile("cp.async.commit_group;\n" ::: "memory");
}
template<int N> __device__ __forceinline__ void cp_wait() {
    asm volatile("cp.async.wait_group %0;\n" :: "n"(N) : "memory");
}
__device__ __forceinline__ void ldsm_x4(uint32_t* r, uint32_t addr) {
    asm volatile("ldmatrix.sync.aligned.m8n8.x4.shared.b16 {%0,%1,%2,%3}, [%4];\n"
                 : "=r"(r[0]), "=r"(r[1]), "=r"(r[2]), "=r"(r[3]) : "r"(addr));
}
__device__ __forceinline__ void mma_16816(float* c, const uint32_t* a, const uint32_t* b) {
    asm volatile("mma.sync.aligned.m16n8k16.row.col.f32.bf16.bf16.f32 "
                 "{%0,%1,%2,%3}, {%4,%5,%6,%7}, {%8,%9}, {%0,%1,%2,%3};\n"
                 : "+f"(c[0]), "+f"(c[1]), "+f"(c[2]), "+f"(c[3])
                 : "r"(a[0]), "r"(a[1]), "r"(a[2]), "r"(a[3]), "r"(b[0]), "r"(b[1]));
}

// ---------------- scratch (device globals) ----------------------------------
__device__ __align__(16) float g_hs[(size_t)BB * NN * DD];   // [B,N,D]
__device__ __align__(16) float g_m[BB * TWO_D];              // [B,2D] fp32
__device__ __align__(16) float g_c[BB * DD];                 // [B,D]
__device__ __align__(16) float g_gpre[BB * 4 * DD];          // [B,2048]
__device__ __align__(16) float g_query[BB * DD];             // [B,D]
// bf16 hi/lo operand copies
__device__ __align__(16) __nv_bfloat16 g_x_hi[(size_t)BB * NN * DD];
__device__ __align__(16) __nv_bfloat16 g_x_lo[(size_t)BB * NN * DD];
__device__ __align__(16) __nv_bfloat16 g_m_hi[BB * TWO_D];
__device__ __align__(16) __nv_bfloat16 g_m_lo[BB * TWO_D];
// packed transposed weights [N][K] bf16 hi/lo
__device__ __align__(16) __nv_bfloat16 g_fc_hi[DD * DD];
__device__ __align__(16) __nv_bfloat16 g_fc_lo[DD * DD];
__device__ __align__(16) __nv_bfloat16 g_wg_hi[4 * DD * TWO_D];
__device__ __align__(16) __nv_bfloat16 g_wg_lo[4 * DD * TWO_D];
__device__ __align__(16) __nv_bfloat16 g_q_hi[DD * DD];
__device__ __align__(16) __nv_bfloat16 g_q_lo[DD * DD];

__device__ __forceinline__ float sigmoidf_(float x) { return 1.0f / (1.0f + expf(-x)); }

// ---------------- tile copy: gmem bf16 [rows][ld] -> smem SW128 -------------
template<int ROWS>
__device__ __forceinline__ void copy_tile(uint32_t sbase, const __nv_bfloat16* __restrict__ g,
                                          int ldg, int r0, int k0, int t) {
#pragma unroll
    for (int v = t; v < ROWS * 8; v += 256) {
        int row = v >> 3, ch = v & 7;
        uint32_t off = SWZ((uint32_t)(row * 128 + ch * 16));
        cp_async16(sbase + off, g + (size_t)(r0 + row) * ldg + k0 + ch * 8);
    }
}

// ---------------- bf16-split HMMA GEMM --------------------------------------
// C[M,N] = (Ahi+Alo)[M,K] @ (Bhi+Blo)^T, B stored [N][K]. 3-term split, fp32 acc.
// Block BMxBN, K-block 64, double-buffered cp.async, 256 threads (8 warps).
template<int BM, int BN, int WM, int WN>
__global__ void __launch_bounds__(256, 2)
mma_gemm_kernel(int K,
                const __nv_bfloat16* __restrict__ Ahi, const __nv_bfloat16* __restrict__ Alo, int lda,
                const __nv_bfloat16* __restrict__ Bhi, const __nv_bfloat16* __restrict__ Blo, int ldb,
                float* __restrict__ C, int ldc, const float* __restrict__ bias)
{
    constexpr int WTM = BM / WM, WTN = BN / WN;
    constexpr int MT = WTM / 16, NT = WTN / 8, NP = NT / 2;
    constexpr int STAGE = (2 * BM + 2 * BN) * 128;
    static_assert(WM * WN == 8 && MT >= 1 && NP >= 1, "cfg");

    extern __shared__ char smem[];
    const int t = threadIdx.x, lane = t & 31, wid = t >> 5;
    const int wm = wid % WM, wn = wid / WM;
    const int m0 = blockIdx.y * BM, n0 = blockIdx.x * BN;
    const uint32_t sbase = (uint32_t)__cvta_generic_to_shared(smem);

    float c[MT][NT][4];
#pragma unroll
    for (int i = 0; i < MT; i++)
#pragma unroll
        for (int j = 0; j < NT; j++)
#pragma unroll
            for (int q = 0; q < 4; q++) c[i][j][q] = 0.0f;

    const int NB = K >> 6;

    auto issue = [&](int kb, int buf) {
        uint32_t st = sbase + (uint32_t)buf * STAGE;
        copy_tile<BM>(st,                           Ahi, lda, m0, kb * 64, t);
        copy_tile<BM>(st + BM * 128,                Alo, lda, m0, kb * 64, t);
        copy_tile<BN>(st + 2 * BM * 128,            Bhi, ldb, n0, kb * 64, t);
        copy_tile<BN>(st + 2 * BM * 128 + BN * 128, Blo, ldb, n0, kb * 64, t);
        cp_commit();
    };

    issue(0, 0);
    issue(1, 1);

    for (int kb = 0; kb < NB; kb++) {
        if (kb + 1 < NB) cp_wait<1>(); else cp_wait<0>();
        __syncthreads();
        const uint32_t st  = sbase + (uint32_t)(kb & 1) * STAGE;
        const uint32_t aHi = st, aLo = st + BM * 128;
        const uint32_t bHi = st + 2 * BM * 128, bLo = bHi + BN * 128;

#pragma unroll
        for (int s = 0; s < 4; s++) {
            uint32_t ahf[MT][4], alf[MT][4];
            const int      arow  = wm * WTM + (lane & 15);
            const uint32_t abyte = s * 32 + ((lane >> 4) << 4);
#pragma unroll
            for (int i = 0; i < MT; i++) {
                uint32_t off = SWZ((uint32_t)((arow + i * 16) * 128) + abyte);
                ldsm_x4(ahf[i], aHi + off);
                ldsm_x4(alf[i], aLo + off);
            }
            uint32_t bhf[NP][4], blf[NP][4];
            const int      brow  = wn * WTN + ((lane >> 4) << 3) + (lane & 7);
            const uint32_t bbyte = s * 32 + (((lane >> 3) & 1) << 4);
#pragma unroll
            for (int p = 0; p < NP; p++) {
                uint32_t off = SWZ((uint32_t)((brow + p * 16) * 128) + bbyte);
                ldsm_x4(bhf[p], bHi + off);
                ldsm_x4(blf[p], bLo + off);
            }
#pragma unroll
            for (int i = 0; i < MT; i++)
#pragma unroll
                for (int j = 0; j < NT; j++) {
                    const uint32_t* bh = &bhf[j >> 1][(j & 1) * 2];
                    const uint32_t* bl = &blf[j >> 1][(j & 1) * 2];
                    mma_16816(c[i][j], ahf[i], bh);
                    mma_16816(c[i][j], ahf[i], bl);
                    mma_16816(c[i][j], alf[i], bh);
                }
        }
        __syncthreads();
        if (kb + 2 < NB) issue(kb + 2, kb & 1);
    }

    // writeout
    const int wr = m0 + wm * WTM, wc = n0 + wn * WTN;
#pragma unroll
    for (int i = 0; i < MT; i++) {
        int r0 = wr + i * 16 + (lane >> 2);
#pragma unroll
        for (int j = 0; j < NT; j++) {
            int col = wc + j * 8 + (lane & 3) * 2;
            float bx = 0.0f, by = 0.0f;
            if (bias) { bx = bias[col]; by = bias[col + 1]; }
            float2 v0 = make_float2(c[i][j][0] + bx, c[i][j][1] + by);
            float2 v1 = make_float2(c[i][j][2] + bx, c[i][j][3] + by);
            *(float2*)&C[(size_t)r0 * ldc + col]       = v0;
            *(float2*)&C[(size_t)(r0 + 8) * ldc + col] = v1;
        }
    }
}

// ---------------- conversion / pack kernels ---------------------------------
__global__ void conv_x_kernel(const float* __restrict__ X) {
    int i = blockIdx.x * blockDim.x + threadIdx.x;      // over float4s
    const int n4 = (int)((size_t)BB * NN * DD / 4);
    if (i >= n4) return;
    float4 x = ((const float4*)X)[i];
    __nv_bfloat16 h0 = __float2bfloat16_rn(x.x), h1 = __float2bfloat16_rn(x.y);
    __nv_bfloat16 h2 = __float2bfloat16_rn(x.z), h3 = __float2bfloat16_rn(x.w);
    __nv_bfloat162 hh0(h0, h1), hh1(h2, h3);
    __nv_bfloat162 ll0(__float2bfloat16_rn(x.x - __bfloat162float(h0)),
                       __float2bfloat16_rn(x.y - __bfloat162float(h1)));
    __nv_bfloat162 ll1(__float2bfloat16_rn(x.z - __bfloat162float(h2)),
                       __float2bfloat16_rn(x.w - __bfloat162float(h3)));
    ((uint2*)g_x_hi)[i] = make_uint2(*(uint32_t*)&hh0, *(uint32_t*)&hh1);
    ((uint2*)g_x_lo)[i] = make_uint2(*(uint32_t*)&ll0, *(uint32_t*)&ll1);
}

// tiled transpose pack: w[K][N] row-major -> out_hi/lo[N][K] bf16, coalesced both sides
__global__ void packT_kernel(const float* __restrict__ w,
                             __nv_bfloat16* __restrict__ hi, __nv_bfloat16* __restrict__ lo,
                             int K, int N) {
    __shared__ float s[32][33];
    const int n0 = blockIdx.x * 32, k0 = blockIdx.y * 32;
    const int tx = threadIdx.x & 31, ty = threadIdx.x >> 5;   // 32 x 8
#pragma unroll
    for (int i = 0; i < 4; i++) {
        int k = k0 + ty + i * 8;
        s[ty + i * 8][tx] = w[(size_t)k * N + n0 + tx];
    }
    __syncthreads();
#pragma unroll
    for (int i = 0; i < 4; i++) {
        int n = n0 + ty + i * 8;
        float x = s[tx][ty + i * 8];
        __nv_bfloat16 h = __float2bfloat16_rn(x);
        size_t o = (size_t)n * K + k0 + tx;
        hi[o] = h;
        lo[o] = __float2bfloat16_rn(x - __bfloat162float(h));
    }
}

// ---------------- elementwise / attention ------------------------------------
__global__ void zero_mc_kernel() {
    int i = blockIdx.x * blockDim.x + threadIdx.x;
    if (i < BB * TWO_D) {
        g_m[i] = 0.0f;
        g_m_hi[i] = __float2bfloat16_rn(0.0f);
        g_m_lo[i] = __float2bfloat16_rn(0.0f);
    }
    if (i < BB * DD) g_c[i] = 0.0f;
}

__global__ void combine_kernel(const float* __restrict__ bi, const float* __restrict__ bf,
                               const float* __restrict__ bc, const float* __restrict__ bo) {
    const int b = blockIdx.x;
    const int j = threadIdx.x;
    const size_t base = (size_t)b * (4 * DD);
    float ip = g_gpre[base + j]           + bi[j];
    float fp = g_gpre[base + DD + j]      + bf[j];
    float cp = g_gpre[base + 2 * DD + j]  + bc[j];
    float op = g_gpre[base + 3 * DD + j]  + bo[j];
    float cold = g_c[b * DD + j];
    float cn = sigmoidf_(fp) * cold + sigmoidf_(ip) * tanhf(cp);
    g_c[b * DD + j] = cn;
    float v = sigmoidf_(op) * tanhf(cn);
    g_m[b * TWO_D + j] = v;
    __nv_bfloat16 h = __float2bfloat16_rn(v);
    g_m_hi[b * TWO_D + j] = h;
    g_m_lo[b * TWO_D + j] = __float2bfloat16_rn(v - __bfloat162float(h));
}

__global__ void __launch_bounds__(128)
attention_kernel(const float* __restrict__ mask, const float* __restrict__ att_v) {
    __shared__ float hs_s[NN][DH + 1];
    __shared__ float qv[DH];
    __shared__ float av[DH];
    __shared__ float red[NN];
    __shared__ float attn[NN];

    const int t = threadIdx.x;
    const int b = blockIdx.x >> 3;
    const int h = blockIdx.x & 7;

    const float* hs_base = g_hs + (size_t)b * NN * DD + h * DH;
    for (int i = t; i < NN * DH; i += 128) {
        int n = i >> 6, d = i & 63;
        hs_s[n][d] = hs_base[(size_t)n * DD + d];
    }
    if (t < DH) {
        qv[t] = g_query[b * DD + h * DH + t];
        av[t] = att_v[h * DH + t];
    }
    __syncthreads();

    float e = 0.0f;
#pragma unroll 8
    for (int d = 0; d < DH; d++) e += tanhf(qv[d] + hs_s[t][d]) * av[d];
    e += (1.0f - mask[b * NN + t]) * (-1e10f);

    red[t] = e;
    __syncthreads();
#pragma unroll
    for (int s = 64; s > 0; s >>= 1) {
        if (t < s) red[t] = fmaxf(red[t], red[t + s]);
        __syncthreads();
    }
    const float mx = red[0];
    __syncthreads();

    float p = expf(e - mx);
    attn[t] = p; red[t] = p;
    __syncthreads();
#pragma unroll
    for (int s = 64; s > 0; s >>= 1) {
        if (t < s) red[t] += red[t + s];
        __syncthreads();
    }
    const float inv_sum = 1.0f / red[0];
    __syncthreads();
    attn[t] *= inv_sum;
    __syncthreads();

    if (t < DH) {
        float r = 0.0f;
#pragma unroll 8
        for (int n = 0; n < NN; n++) r += attn[n] * hs_s[n][t];
        int col = DD + h * DH + t;
        g_m[b * TWO_D + col] = r;
        __nv_bfloat16 hh = __float2bfloat16_rn(r);
        g_m_hi[b * TWO_D + col] = hh;
        g_m_lo[b * TWO_D + col] = __float2bfloat16_rn(r - __bfloat162float(hh));
    }
}

__global__ void copy_out_kernel(float* __restrict__ out) {
    int i = blockIdx.x * blockDim.x + threadIdx.x;
    if (i < BB * TWO_D) out[i] = g_m[i];
}

// ---------------- launcher ----------------------------------------------------
extern "C" void kernel_launch(void* const* d_in, const int* in_sizes, int n_in,
                              void* d_out, int out_size) {
    const float* X     = (const float*)d_in[0];
    const float* mask  = (const float*)d_in[1];
    const float* fc_w  = (const float*)d_in[2];
    const float* fc_b  = (const float*)d_in[3];
    const float* w_im  = (const float*)d_in[4];
    const float* b_i   = (const float*)d_in[5];
    const float* w_fm  = (const float*)d_in[6];
    const float* b_f   = (const float*)d_in[7];
    const float* w_cm  = (const float*)d_in[8];
    const float* b_c   = (const float*)d_in[9];
    const float* w_om  = (const float*)d_in[10];
    const float* b_o   = (const float*)d_in[11];
    const float* m2q   = (const float*)d_in[12];
    const float* att_v = (const float*)d_in[13];
    float* out = (float*)d_out;

    float *p_hs, *p_gpre, *p_query;
    __nv_bfloat16 *p_x_hi, *p_x_lo, *p_m_hi, *p_m_lo;
    __nv_bfloat16 *p_fc_hi, *p_fc_lo, *p_wg_hi, *p_wg_lo, *p_q_hi, *p_q_lo;
    cudaGetSymbolAddress((void**)&p_hs,    g_hs);
    cudaGetSymbolAddress((void**)&p_gpre,  g_gpre);
    cudaGetSymbolAddress((void**)&p_query, g_query);
    cudaGetSymbolAddress((void**)&p_x_hi,  g_x_hi);
    cudaGetSymbolAddress((void**)&p_x_lo,  g_x_lo);
    cudaGetSymbolAddress((void**)&p_m_hi,  g_m_hi);
    cudaGetSymbolAddress((void**)&p_m_lo,  g_m_lo);
    cudaGetSymbolAddress((void**)&p_fc_hi, g_fc_hi);
    cudaGetSymbolAddress((void**)&p_fc_lo, g_fc_lo);
    cudaGetSymbolAddress((void**)&p_wg_hi, g_wg_hi);
    cudaGetSymbolAddress((void**)&p_wg_lo, g_wg_lo);
    cudaGetSymbolAddress((void**)&p_q_hi,  g_q_hi);
    cudaGetSymbolAddress((void**)&p_q_lo,  g_q_lo);

    // smem sizes per instantiation (2 stages each)
    const int SM_PROJ  = (2 * 128 + 2 * 64) * 128 * 2;  // 98304  -> 2 CTAs/SM
    const int SM_GATE  = (2 * 64  + 2 * 64) * 128 * 2;  // 65536  -> 3 CTAs/SM
    const int SM_QUERY = (2 * 32  + 2 * 64) * 128 * 2;  // 49152  -> 4 CTAs/SM
    cudaFuncSetAttribute((const void*)mma_gemm_kernel<128, 64, 2, 4>,
                         cudaFuncAttributeMaxDynamicSharedMemorySize, SM_PROJ);
    cudaFuncSetAttribute((const void*)mma_gemm_kernel<64, 64, 2, 4>,
                         cudaFuncAttributeMaxDynamicSharedMemorySize, SM_GATE);
    cudaFuncSetAttribute((const void*)mma_gemm_kernel<32, 64, 2, 4>,
                         cudaFuncAttributeMaxDynamicSharedMemorySize, SM_QUERY);

    zero_mc_kernel<<<(BB * TWO_D + 255) / 256, 256>>>();
    conv_x_kernel<<<((int)((size_t)BB * NN * DD / 4) + 255) / 256, 256>>>(X);
    // weight packs: coalesced tiled transpose
    {
        dim3 gfc(DD / 32, DD / 32);
        packT_kernel<<<gfc, 256>>>(fc_w, p_fc_hi, p_fc_lo, DD, DD);
        packT_kernel<<<gfc, 256>>>(m2q,  p_q_hi,  p_q_lo,  DD, DD);
        dim3 gg(DD / 32, TWO_D / 32);   // each gate: w[1024][512] -> [512][1024]
        packT_kernel<<<gg, 256>>>(w_im, p_wg_hi + 0 * DD * TWO_D, p_wg_lo + 0 * DD * TWO_D, TWO_D, DD);
        packT_kernel<<<gg, 256>>>(w_fm, p_wg_hi + 1 * DD * TWO_D, p_wg_lo + 1 * DD * TWO_D, TWO_D, DD);
        packT_kernel<<<gg, 256>>>(w_cm, p_wg_hi + 2 * DD * TWO_D, p_wg_lo + 2 * DD * TWO_D, TWO_D, DD);
        packT_kernel<<<gg, 256>>>(w_om, p_wg_hi + 3 * DD * TWO_D, p_wg_lo + 3 * DD * TWO_D, TWO_D, DD);
    }

    // projection: hs = X @ fc_w + fc_b   (M=65536, N=512, K=512)
    {
        dim3 grid(DD / 64, (BB * NN) / 128);
        mma_gemm_kernel<128, 64, 2, 4><<<grid, 256, SM_PROJ>>>(
            DD, p_x_hi, p_x_lo, DD, p_fc_hi, p_fc_lo, DD, p_hs, DD, fc_b);
    }

    for (int step = 0; step < STEPS; step++) {
        // gates: m[512,1024] @ Wg^T -> gpre[512,2048]
        {
            dim3 grid((4 * DD) / 64, BB / 64);
            mma_gemm_kernel<64, 64, 2, 4><<<grid, 256, SM_GATE>>>(
                TWO_D, p_m_hi, p_m_lo, TWO_D, p_wg_hi, p_wg_lo, TWO_D,
                p_gpre, 4 * DD, nullptr);
        }
        combine_kernel<<<BB, DD>>>(b_i, b_f, b_c, b_o);

        // query = m_lstm @ m2q  (A = m_hi/lo[:, :512], lda=1024)
        {
            dim3 grid(DD / 64, BB / 32);
            mma_gemm_kernel<32, 64, 2, 4><<<grid, 256, SM_QUERY>>>(
                DD, p_m_hi, p_m_lo, TWO_D, p_q_hi, p_q_lo, DD,
                p_query, DD, nullptr);
        }
        attention_kernel<<<BB * HH, 128>>>(mask, att_v);
    }

    copy_out_kernel<<<(BB * TWO_D + 255) / 256, 256>>>(out);
}